// round 16
// baseline (speedup 1.0000x reference)
#include <cuda_runtime.h>
#include <cuda_bf16.h>
#include <math.h>

#define NN 50000
#define EE 600000
#define NSTEPS 5
#define NB4 (4 * NN + 1)    // CSR bins: (dst,etype)
#define NSB 391             // scan blocks: 391*512 >= 4*NN

// ---------------- scratch (device globals) ----------------
__device__ float g_gig[(size_t)2 * NN * 768];   // [gi(384) | gh(384)]; reused as GAT out [2N,256]
__device__ float g_h[(size_t)2 * NN * 128];
__device__ float g_cb[(size_t)2 * NN * 128];    // count-weighted b_et sum per node
__device__ float g_zft[(size_t)2 * NN * 256];
__device__ float g_el[2 * NN * 2];
__device__ float g_er[2 * NN * 2];
__device__ int   g_indptr[2 * NB4];
__device__ int   g_cursor[2 * NB4];
__device__ int   g_bsum[2][512];
__device__ int   g_eids[2 * EE];                // stores src directly (CSR by dst*4+et)
__device__ int   g_goff[2 * 65];
__device__ float g_part[2 * 64 * 16 * 256];
__device__ float g_hg[2 * 64 * 256];
__device__ float g_logits[2 * 64 * 2 * 32];
__device__ float g_zerobias[512];

// bf16 split buffers
__device__ __nv_bfloat16 g_cvhh[(size_t)2 * NN * 128];  // h split
__device__ __nv_bfloat16 g_cvhl[(size_t)2 * NN * 128];
__device__ __nv_bfloat16 g_sh[(size_t)2 * NN * 512];    // s (per-etype h sums) split
__device__ __nv_bfloat16 g_sl[(size_t)2 * NN * 512];
__device__ __nv_bfloat16 g_cvah[(size_t)2 * NN * 128];  // a split
__device__ __nv_bfloat16 g_cval[(size_t)2 * NN * 128];
__device__ __nv_bfloat16 g_WAh[128 * 512];              // stacked W_et: [o][k*128+d]
__device__ __nv_bfloat16 g_WAl[128 * 512];
__device__ __nv_bfloat16 g_Wihh[384 * 128];
__device__ __nv_bfloat16 g_Wihl[384 * 128];
__device__ __nv_bfloat16 g_Whhh[384 * 128];
__device__ __nv_bfloat16 g_Whhl[384 * 128];
__device__ __nv_bfloat16 g_Wfch[256 * 128];
__device__ __nv_bfloat16 g_Wfcl[256 * 128];

__device__ __forceinline__ float sigf(float x) { return 1.0f / (1.0f + expf(-x)); }
__device__ __forceinline__ float leakyf(float x) { return x > 0.0f ? x : 0.2f * x; }

__device__ __forceinline__ void split2(float x, __nv_bfloat16* hi, __nv_bfloat16* lo) {
    __nv_bfloat16 h = __float2bfloat16(x);
    *hi = h;
    *lo = __float2bfloat16(x - __bfloat162float(h));
}

__device__ __forceinline__ void split4_store(float4 v, __nv_bfloat16* hi, __nv_bfloat16* lo) {
    __nv_bfloat16 h0, h1, h2, h3, l0, l1, l2, l3;
    split2(v.x, &h0, &l0); split2(v.y, &h1, &l1);
    split2(v.z, &h2, &l2); split2(v.w, &h3, &l3);
    uint2 ph = make_uint2(((unsigned)__bfloat16_as_ushort(h1) << 16) | __bfloat16_as_ushort(h0),
                          ((unsigned)__bfloat16_as_ushort(h3) << 16) | __bfloat16_as_ushort(h2));
    uint2 pl = make_uint2(((unsigned)__bfloat16_as_ushort(l1) << 16) | __bfloat16_as_ushort(l0),
                          ((unsigned)__bfloat16_as_ushort(l3) << 16) | __bfloat16_as_ushort(l2));
    *(uint2*)hi = ph;
    *(uint2*)lo = pl;
}

// ---------------- prep: weight splits + h init + cursor zero + graph offsets ----------------
__global__ void prep_all(const float* __restrict__ f0, const float* __restrict__ f1,
                         const float* __restrict__ Wet, const float* __restrict__ Wih,
                         const float* __restrict__ Whh, const float* __restrict__ Wfc,
                         const int* __restrict__ gid0, const int* __restrict__ gid1) {
    int idx = blockIdx.x * 256 + threadIdx.x;
    if (idx < 2 * NN * 128) {
        float x = (idx < NN * 128) ? f0[idx] : f1[idx - NN * 128];
        g_h[idx] = x;
        split2(x, g_cvhh + idx, g_cvhl + idx);
    }
    if (idx < 128 * 512) {   // stacked W_et: WA[o][k*128+d] = W_et[k][o][d]
        int o = idx >> 9, kk = idx & 511;
        int k = kk >> 7, d = kk & 127;
        split2(Wet[(k << 14) + (o << 7) + d], g_WAh + idx, g_WAl + idx);
    }
    if (idx < 384 * 128) {
        split2(Wih[idx], g_Wihh + idx, g_Wihl + idx);
        split2(Whh[idx], g_Whhh + idx, g_Whhl + idx);
    }
    if (idx < 256 * 128) split2(Wfc[idx], g_Wfch + idx, g_Wfcl + idx);
    if (idx < 2 * NB4) g_cursor[idx] = 0;
    if (idx < 2 * 65) {      // graph offsets by binary search on sorted gid
        int inst = idx / 65, g = idx % 65;
        const int* gid = inst ? gid1 : gid0;
        int lo = 0, hi = NN;
        while (lo < hi) {
            int mid = (lo + hi) >> 1;
            if (gid[mid] < g) lo = mid + 1; else hi = mid;
        }
        g_goff[idx] = lo;
    }
}

// ---------------- CSR build keyed by dst*4+etype ----------------
__global__ void hist_kernel(const int* __restrict__ d0, const int* __restrict__ e0,
                            const int* __restrict__ d1, const int* __restrict__ e1) {
    int i = blockIdx.x * 256 + threadIdx.x;
    if (i >= EE) return;
    int inst = blockIdx.y;
    const int* dst = inst ? d1 : d0;
    const int* et  = inst ? e1 : e0;
    atomicAdd(&g_cursor[inst * NB4 + dst[i] * 4 + et[i]], 1);
}

// 3-phase parallel exclusive scan of g_cursor[inst][0..4NN) -> g_indptr, g_cursor
__global__ void scan1_kernel() {
    int inst = blockIdx.y;
    int base = blockIdx.x * 512;
    int tid = threadIdx.x;
    const int n = 4 * NN;
    const int* cur = g_cursor + inst * NB4;
    int i0 = base + tid * 2;
    int v0 = (i0 < n) ? cur[i0] : 0;
    int v1 = (i0 + 1 < n) ? cur[i0 + 1] : 0;
    __shared__ int sm[256];
    sm[tid] = v0 + v1;
    __syncthreads();
    for (int o = 128; o; o >>= 1) {
        if (tid < o) sm[tid] += sm[tid + o];
        __syncthreads();
    }
    if (tid == 0) g_bsum[inst][blockIdx.x] = sm[0];
}

__global__ void scan2_kernel() {
    int inst = blockIdx.x;
    int tid = threadIdx.x;   // 512 threads
    __shared__ int sm[512];
    int v = (tid < NSB) ? g_bsum[inst][tid] : 0;
    sm[tid] = v;
    __syncthreads();
    for (int o = 1; o < 512; o <<= 1) {
        int t = (tid >= o) ? sm[tid - o] : 0;
        __syncthreads();
        sm[tid] += t;
        __syncthreads();
    }
    if (tid < NSB) g_bsum[inst][tid] = sm[tid] - v;   // exclusive
}

__global__ void scan3_kernel() {
    int inst = blockIdx.y;
    int base = blockIdx.x * 512;
    int tid = threadIdx.x;
    const int n = 4 * NN;
    int* cur = g_cursor + inst * NB4;
    int* ip = g_indptr + inst * NB4;
    int i0 = base + tid * 2;
    int v0 = (i0 < n) ? cur[i0] : 0;
    int v1 = (i0 + 1 < n) ? cur[i0 + 1] : 0;
    __shared__ int sm[256];
    int pair = v0 + v1;
    sm[tid] = pair;
    __syncthreads();
    for (int o = 1; o < 256; o <<= 1) {
        int t = (tid >= o) ? sm[tid - o] : 0;
        __syncthreads();
        sm[tid] += t;
        __syncthreads();
    }
    int excl = sm[tid] - pair + g_bsum[inst][blockIdx.x];
    if (i0 < n)     { ip[i0] = excl;        cur[i0] = excl; }
    if (i0 + 1 < n) { ip[i0 + 1] = excl + v0; cur[i0 + 1] = excl + v0; }
    if (blockIdx.x == 0 && tid == 0) ip[n] = EE;   // total is exactly EE
}

__global__ void scatter_kernel(const int* __restrict__ s0, const int* __restrict__ d0,
                               const int* __restrict__ e0, const int* __restrict__ s1,
                               const int* __restrict__ d1, const int* __restrict__ e1) {
    int i = blockIdx.x * 256 + threadIdx.x;
    if (i >= EE) return;
    int inst = blockIdx.y;
    const int* src = inst ? s1 : s0;
    const int* dst = inst ? d1 : d0;
    const int* et  = inst ? e1 : e0;
    int pos = atomicAdd(&g_cursor[inst * NB4 + dst[i] * 4 + et[i]], 1);
    g_eids[inst * EE + pos] = src[i];
}

// ---------------- tensor-core GEMM, double-buffered cp.async pipeline ----------------
__device__ __forceinline__ void ldsm_x4(unsigned& r0, unsigned& r1, unsigned& r2, unsigned& r3,
                                        unsigned addr) {
    asm volatile("ldmatrix.sync.aligned.m8n8.x4.shared.b16 {%0,%1,%2,%3}, [%4];\n"
                 : "=r"(r0), "=r"(r1), "=r"(r2), "=r"(r3) : "r"(addr));
}

__device__ __forceinline__ void mma_bf16(float* c, const unsigned* a, const unsigned* b) {
    asm volatile(
        "mma.sync.aligned.m16n8k16.row.col.f32.bf16.bf16.f32 "
        "{%0,%1,%2,%3},{%4,%5,%6,%7},{%8,%9},{%0,%1,%2,%3};\n"
        : "+f"(c[0]), "+f"(c[1]), "+f"(c[2]), "+f"(c[3])
        : "r"(a[0]), "r"(a[1]), "r"(a[2]), "r"(a[3]), "r"(b[0]), "r"(b[1]));
}

__device__ __forceinline__ void cp_async16(unsigned dst, const void* src, bool valid) {
    int sz = valid ? 16 : 0;
    asm volatile("cp.async.cg.shared.global [%0], [%1], 16, %2;\n"
                 :: "r"(dst), "l"(src), "r"(sz));
}

#define LDC 72                                   // padded k-stride (elems): 144B rows
#define STG_BYTES ((128 * LDC + 64 * LDC) * 2 * 2)   // 55296 per stage
#define SMEM_GEMM_BYTES (2 * STG_BYTES)              // 110592 (2 stages)

// stage one 64-wide K chunk into the stage at sbase
__device__ __forceinline__ void gemm_issue(
    unsigned sbase,
    const __nv_bfloat16* __restrict__ Ahi, const __nv_bfloat16* __restrict__ Alo,
    const __nv_bfloat16* __restrict__ Bhi, const __nv_bfloat16* __restrict__ Blo,
    int brow, int bcol, int ko, int KTOT, int tid)
{
    unsigned sAh = sbase;
    unsigned sAl = sbase + 128 * LDC * 2;
    unsigned sBh = sbase + 256 * LDC * 2;
    unsigned sBl = sbase + 320 * LDC * 2;
#pragma unroll
    for (int it = 0; it < 4; it++) {
        int u = tid + it * 256;
        int r = u >> 3, cu = (u & 7) << 3;
        int gr = brow + r;
        bool v = gr < NN;
        size_t grc = v ? (size_t)gr : 0;
        cp_async16(sAh + (r * LDC + cu) * 2, Ahi + grc * KTOT + ko + cu, v);
        cp_async16(sAl + (r * LDC + cu) * 2, Alo + grc * KTOT + ko + cu, v);
    }
#pragma unroll
    for (int it = 0; it < 2; it++) {
        int u = tid + it * 256;
        int r = u >> 3, cu = (u & 7) << 3;
        cp_async16(sBh + (r * LDC + cu) * 2, Bhi + (size_t)(bcol + r) * KTOT + ko + cu, true);
        cp_async16(sBl + (r * LDC + cu) * 2, Blo + (size_t)(bcol + r) * KTOT + ko + cu, true);
    }
    asm volatile("cp.async.commit_group;\n");
}

// C[NN, nout] = A[NN, CH*64] x B[nout, CH*64]^T, hi/lo 3-term split, 2-stage pipeline.
template <int CH, bool SPLIT, bool ROWADD>
__global__ void __launch_bounds__(256, 2) gemm_mma(
    const __nv_bfloat16* __restrict__ Ahi, const __nv_bfloat16* __restrict__ Alo,
    const __nv_bfloat16* __restrict__ Bhi, const __nv_bfloat16* __restrict__ Blo,
    const float* __restrict__ bias, const float* __restrict__ rowadd,
    float* __restrict__ Cf, __nv_bfloat16* __restrict__ Csh, __nv_bfloat16* __restrict__ Csl,
    int rs)
{
    extern __shared__ __nv_bfloat16 sm[];
    const unsigned sb0 = (unsigned)__cvta_generic_to_shared(sm);
    const unsigned sb1 = sb0 + (unsigned)STG_BYTES;

    const int inst = blockIdx.z;
    const int KTOT = CH * 64;
    Ahi += (size_t)inst * NN * KTOT;
    Alo += (size_t)inst * NN * KTOT;
    if (SPLIT) {
        Csh += (size_t)inst * NN * 128;
        Csl += (size_t)inst * NN * 128;
    } else {
        Cf += (size_t)inst * NN * rs;
    }
    if (ROWADD) rowadd += (size_t)inst * NN * 128;

    const int tid = threadIdx.x;
    const int brow = blockIdx.y * 128;
    const int bcol = blockIdx.x * 64;

    const int wid = tid >> 5, lane = tid & 31;
    const int wr = (wid & 3) * 32;
    const int wc = (wid >> 2) * 32;

    float acc[2][4][4];
#pragma unroll
    for (int mi = 0; mi < 2; mi++)
#pragma unroll
        for (int nj = 0; nj < 4; nj++)
#pragma unroll
            for (int q = 0; q < 4; q++) acc[mi][nj][q] = 0.0f;

    const int la_r = lane & 15;
    const int la_c = (lane & 16) ? 8 : 0;
    const int lb_r = (lane & 7) + ((lane & 16) ? 8 : 0);
    const int lb_c = (lane & 8) ? 8 : 0;

    // prologue: stage chunk 0
    gemm_issue(sb0, Ahi, Alo, Bhi, Blo, brow, bcol, 0, KTOT, tid);

    for (int ch = 0; ch < CH; ch++) {
        unsigned cur = (ch & 1) ? sb1 : sb0;
        if (ch + 1 < CH) {
            // prefetch next chunk into the other stage (free: its last readers
            // synced at the end of iteration ch-1)
            gemm_issue((ch & 1) ? sb0 : sb1, Ahi, Alo, Bhi, Blo,
                       brow, bcol, (ch + 1) * 64, KTOT, tid);
            asm volatile("cp.async.wait_group 1;\n");
        } else {
            asm volatile("cp.async.wait_group 0;\n");
        }
        __syncthreads();

        unsigned sAh = cur;
        unsigned sAl = cur + 128 * LDC * 2;
        unsigned sBh = cur + 256 * LDC * 2;
        unsigned sBl = cur + 320 * LDC * 2;
#pragma unroll
        for (int kc = 0; kc < 4; kc++) {
            const int k0 = kc * 16;
            unsigned ah[2][4], al[2][4], bh[4][2], bl[4][2];
#pragma unroll
            for (int mi = 0; mi < 2; mi++) {
                unsigned off = (unsigned)(((wr + mi * 16 + la_r) * LDC + k0 + la_c) * 2);
                ldsm_x4(ah[mi][0], ah[mi][1], ah[mi][2], ah[mi][3], sAh + off);
                ldsm_x4(al[mi][0], al[mi][1], al[mi][2], al[mi][3], sAl + off);
            }
#pragma unroll
            for (int np = 0; np < 2; np++) {
                unsigned off = (unsigned)(((wc + np * 16 + lb_r) * LDC + k0 + lb_c) * 2);
                unsigned r0, r1, r2, r3;
                ldsm_x4(r0, r1, r2, r3, sBh + off);
                bh[np * 2][0] = r0; bh[np * 2][1] = r1;
                bh[np * 2 + 1][0] = r2; bh[np * 2 + 1][1] = r3;
                ldsm_x4(r0, r1, r2, r3, sBl + off);
                bl[np * 2][0] = r0; bl[np * 2][1] = r1;
                bl[np * 2 + 1][0] = r2; bl[np * 2 + 1][1] = r3;
            }
#pragma unroll
            for (int mi = 0; mi < 2; mi++)
#pragma unroll
                for (int nj = 0; nj < 4; nj++) {
                    mma_bf16(acc[mi][nj], ah[mi], bh[nj]);
                    mma_bf16(acc[mi][nj], al[mi], bh[nj]);
                    mma_bf16(acc[mi][nj], ah[mi], bl[nj]);
                }
        }
        __syncthreads();   // all readers done before this stage is refilled
    }

    const int g = lane >> 2, t4 = lane & 3;
#pragma unroll
    for (int mi = 0; mi < 2; mi++) {
#pragma unroll
        for (int nj = 0; nj < 4; nj++) {
            int col = bcol + wc + nj * 8 + t4 * 2;
            float bx = bias[col], by = bias[col + 1];
#pragma unroll
            for (int half = 0; half < 2; half++) {
                int r = brow + wr + mi * 16 + g + half * 8;
                if (r >= NN) continue;
                float v0 = acc[mi][nj][half * 2 + 0] + bx;
                float v1 = acc[mi][nj][half * 2 + 1] + by;
                if (ROWADD) {
                    v0 += rowadd[(size_t)r * 128 + col];
                    v1 += rowadd[(size_t)r * 128 + col + 1];
                }
                if (SPLIT) {
                    __nv_bfloat16 h0, h1, l0, l1;
                    split2(v0, &h0, &l0);
                    split2(v1, &h1, &l1);
                    unsigned ph = ((unsigned)__bfloat16_as_ushort(h1) << 16) | __bfloat16_as_ushort(h0);
                    unsigned pl = ((unsigned)__bfloat16_as_ushort(l1) << 16) | __bfloat16_as_ushort(l0);
                    *(unsigned*)(Csh + (size_t)r * 128 + col) = ph;
                    *(unsigned*)(Csl + (size_t)r * 128 + col) = pl;
                } else {
                    *(float2*)(Cf + (size_t)r * rs + col) = make_float2(v0, v1);
                }
            }
        }
    }
}

// ---------------- aggregate4: flattened bin loop + 4-edge MLP batching ----------------
__global__ void aggregate4_kernel(const float* __restrict__ b_et) {
    int inst = blockIdx.y;
    int n = blockIdx.x * 8 + (threadIdx.x >> 5);
    if (n >= NN) return;
    int lane = threadIdx.x & 31;
    const int* ip = g_indptr + inst * NB4 + n * 4;
    const int* eids = g_eids + (size_t)inst * EE;
    const float* hb = g_h + (size_t)inst * NN * 128;
    int b0 = ip[0], b1 = ip[1], b2 = ip[2], b3 = ip[3], b4 = ip[4];

    float4 a0 = make_float4(0.f, 0.f, 0.f, 0.f);
    float4 a1 = a0, a2 = a0, a3 = a0;
    int co = lane * 4;

    for (int i = b0; i < b4; i += 4) {
        int cnt = b4 - i;
        int s[4];
#pragma unroll
        for (int j = 0; j < 4; j++) s[j] = (j < cnt) ? eids[i + j] : s[0];
        float4 v[4];
#pragma unroll
        for (int j = 0; j < 4; j++) v[j] = *(const float4*)(hb + (size_t)s[j] * 128 + co);
#pragma unroll
        for (int j = 0; j < 4; j++) {
            if (j < cnt) {
                int e = i + j;
                int k = (e >= b1) + (e >= b2) + (e >= b3);   // warp-uniform
                float4 vv = v[j];
                if (k == 0)      { a0.x += vv.x; a0.y += vv.y; a0.z += vv.z; a0.w += vv.w; }
                else if (k == 1) { a1.x += vv.x; a1.y += vv.y; a1.z += vv.z; a1.w += vv.w; }
                else if (k == 2) { a2.x += vv.x; a2.y += vv.y; a2.z += vv.z; a2.w += vv.w; }
                else             { a3.x += vv.x; a3.y += vv.y; a3.z += vv.z; a3.w += vv.w; }
            }
        }
    }

    size_t so = ((size_t)inst * NN + n) * 512 + co;
    split4_store(a0, g_sh + so, g_sl + so);
    split4_store(a1, g_sh + so + 128, g_sl + so + 128);
    split4_store(a2, g_sh + so + 256, g_sl + so + 256);
    split4_store(a3, g_sh + so + 384, g_sl + so + 384);

    float c0 = (float)(b1 - b0), c1 = (float)(b2 - b1);
    float c2 = (float)(b3 - b2), c3 = (float)(b4 - b3);
    float4 e0 = *(const float4*)(b_et + co);
    float4 e1 = *(const float4*)(b_et + 128 + co);
    float4 e2 = *(const float4*)(b_et + 256 + co);
    float4 e3 = *(const float4*)(b_et + 384 + co);
    float4 cbv;
    cbv.x = c0 * e0.x + c1 * e1.x + c2 * e2.x + c3 * e3.x;
    cbv.y = c0 * e0.y + c1 * e1.y + c2 * e2.y + c3 * e3.y;
    cbv.z = c0 * e0.z + c1 * e1.z + c2 * e2.z + c3 * e3.z;
    cbv.w = c0 * e0.w + c1 * e1.w + c2 * e2.w + c3 * e3.w;
    *(float4*)(g_cb + ((size_t)inst * NN + n) * 128 + co) = cbv;
}

// ---------------- GRU elementwise (float4 per thread): h = (1-z)*nn + z*h ----------------
__global__ void gru_kernel() {
    int idx = blockIdx.x * 256 + threadIdx.x;
    if (idx >= 2 * NN * 32) return;
    int n = idx >> 5, c4 = (idx & 31) << 2;
    const float* gg = g_gig + (size_t)n * 768;
    float4 gir = *(const float4*)(gg + c4);
    float4 giz = *(const float4*)(gg + 128 + c4);
    float4 gin = *(const float4*)(gg + 256 + c4);
    float4 ghr = *(const float4*)(gg + 384 + c4);
    float4 ghz = *(const float4*)(gg + 512 + c4);
    float4 ghn = *(const float4*)(gg + 640 + c4);
    size_t ho = (size_t)n * 128 + c4;
    float4 hv = *(float4*)(g_h + ho);
    float4 o;
    {
        float r = sigf(gir.x + ghr.x), z = sigf(giz.x + ghz.x);
        o.x = (1.0f - z) * tanhf(gin.x + r * ghn.x) + z * hv.x;
    }
    {
        float r = sigf(gir.y + ghr.y), z = sigf(giz.y + ghz.y);
        o.y = (1.0f - z) * tanhf(gin.y + r * ghn.y) + z * hv.y;
    }
    {
        float r = sigf(gir.z + ghr.z), z = sigf(giz.z + ghz.z);
        o.z = (1.0f - z) * tanhf(gin.z + r * ghn.z) + z * hv.z;
    }
    {
        float r = sigf(gir.w + ghr.w), z = sigf(giz.w + ghz.w);
        o.w = (1.0f - z) * tanhf(gin.w + r * ghn.w) + z * hv.w;
    }
    *(float4*)(g_h + ho) = o;
    split4_store(o, g_cvhh + ho, g_cvhl + ho);
}

// ---------------- L2 normalize + sigmoid; emit h split ----------------
__global__ void normsig_kernel() {
    int w = (blockIdx.x * blockDim.x + threadIdx.x) >> 5;
    if (w >= 2 * NN) return;
    int lane = threadIdx.x & 31;
    size_t o = (size_t)w * 128 + lane * 4;
    float4 v = *(float4*)(g_h + o);
    float ss = v.x * v.x + v.y * v.y + v.z * v.z + v.w * v.w;
    for (int of = 16; of; of >>= 1) ss += __shfl_xor_sync(0xffffffff, ss, of);
    float inv = 1.0f / fmaxf(sqrtf(ss), 1e-12f);
    v.x = sigf(v.x * inv); v.y = sigf(v.y * inv);
    v.z = sigf(v.z * inv); v.w = sigf(v.w * inv);
    *(float4*)(g_h + o) = v;
    split4_store(v, g_cvhh + o, g_cvhl + o);
}

// ---------------- GAT: el/er per node ----------------
__global__ void elr_kernel(const float* __restrict__ al, const float* __restrict__ ar) {
    int w = (blockIdx.x * blockDim.x + threadIdx.x) >> 5;
    if (w >= 2 * NN) return;
    int lane = threadIdx.x & 31;
    float4 z0 = *(float4*)(g_zft + (size_t)w * 256 + lane * 4);
    float4 z1 = *(float4*)(g_zft + (size_t)w * 256 + 128 + lane * 4);
    float4 l0v = *(const float4*)(al + lane * 4);
    float4 l1v = *(const float4*)(al + 128 + lane * 4);
    float4 r0v = *(const float4*)(ar + lane * 4);
    float4 r1v = *(const float4*)(ar + 128 + lane * 4);
    float l0 = z0.x * l0v.x + z0.y * l0v.y + z0.z * l0v.z + z0.w * l0v.w;
    float l1 = z1.x * l1v.x + z1.y * l1v.y + z1.z * l1v.z + z1.w * l1v.w;
    float r0 = z0.x * r0v.x + z0.y * r0v.y + z0.z * r0v.z + z0.w * r0v.w;
    float r1 = z1.x * r1v.x + z1.y * r1v.y + z1.z * r1v.z + z1.w * r1v.w;
    for (int o = 16; o; o >>= 1) {
        l0 += __shfl_xor_sync(0xffffffff, l0, o);
        l1 += __shfl_xor_sync(0xffffffff, l1, o);
        r0 += __shfl_xor_sync(0xffffffff, r0, o);
        r1 += __shfl_xor_sync(0xffffffff, r1, o);
    }
    if (lane == 0) {
        g_el[w * 2 + 0] = l0; g_el[w * 2 + 1] = l1;
        g_er[w * 2 + 0] = r0; g_er[w * 2 + 1] = r1;
    }
}

// ---------------- GAT fused: max + den + weighted aggregate (4-edge batched) ----------------
__global__ void gatfused_kernel(const float* __restrict__ gbias) {
    int inst = blockIdx.y;
    int n = blockIdx.x * 8 + (threadIdx.x >> 5);
    if (n >= NN) return;
    int lane = threadIdx.x & 31;
    const int* ip = g_indptr + inst * NB4;
    int beg = ip[n * 4], end = ip[n * 4 + 4];
    const int* eids = g_eids + (size_t)inst * EE;
    float* outb = g_gig + (size_t)inst * NN * 256;
    float4 b0 = *(const float4*)(gbias + lane * 4);
    float4 b1 = *(const float4*)(gbias + 128 + lane * 4);
    if (beg == end) {
        float4 o0 = make_float4(fmaxf(b0.x, 0.f), fmaxf(b0.y, 0.f), fmaxf(b0.z, 0.f), fmaxf(b0.w, 0.f));
        float4 o1 = make_float4(fmaxf(b1.x, 0.f), fmaxf(b1.y, 0.f), fmaxf(b1.z, 0.f), fmaxf(b1.w, 0.f));
        *(float4*)(outb + (size_t)n * 256 + lane * 4) = o0;
        *(float4*)(outb + (size_t)n * 256 + 128 + lane * 4) = o1;
        return;
    }
    int nb = inst * NN + n;
    float er0 = g_er[nb * 2], er1 = g_er[nb * 2 + 1];
    const float* elb = g_el + (size_t)inst * NN * 2;
    float m0 = -INFINITY, m1 = -INFINITY;
    for (int i = beg + lane; i < end; i += 32) {
        int s = eids[i];
        m0 = fmaxf(m0, leakyf(elb[s * 2] + er0));
        m1 = fmaxf(m1, leakyf(elb[s * 2 + 1] + er1));
    }
    for (int o = 16; o; o >>= 1) {
        m0 = fmaxf(m0, __shfl_xor_sync(0xffffffff, m0, o));
        m1 = fmaxf(m1, __shfl_xor_sync(0xffffffff, m1, o));
    }
    float den0 = 0.f, den1 = 0.f;
    for (int i = beg + lane; i < end; i += 32) {
        int s = eids[i];
        den0 += expf(leakyf(elb[s * 2] + er0) - m0);
        den1 += expf(leakyf(elb[s * 2 + 1] + er1) - m1);
    }
    for (int o = 16; o; o >>= 1) {
        den0 += __shfl_xor_sync(0xffffffff, den0, o);
        den1 += __shfl_xor_sync(0xffffffff, den1, o);
    }
    float4 acc0 = make_float4(0.f, 0.f, 0.f, 0.f);
    float4 acc1 = make_float4(0.f, 0.f, 0.f, 0.f);
    int co = lane * 4;
    for (int i = beg; i < end; i += 4) {
        int cnt = end - i;
        int s[4];
#pragma unroll
        for (int j = 0; j < 4; j++) s[j] = (j < cnt) ? eids[i + j] : s[0];
        float w0[4], w1[4];
#pragma unroll
        for (int j = 0; j < 4; j++) {
            w0[j] = expf(leakyf(elb[s[j] * 2] + er0) - m0);
            w1[j] = expf(leakyf(elb[s[j] * 2 + 1] + er1) - m1);
        }
        float4 z0[4], z1[4];
#pragma unroll
        for (int j = 0; j < 4; j++) {
            size_t zb = ((size_t)inst * NN + s[j]) * 256;
            z0[j] = *(const float4*)(g_zft + zb + co);
            z1[j] = *(const float4*)(g_zft + zb + 128 + co);
        }
#pragma unroll
        for (int j = 0; j < 4; j++) {
            if (j < cnt) {
                acc0.x += w0[j] * z0[j].x; acc0.y += w0[j] * z0[j].y;
                acc0.z += w0[j] * z0[j].z; acc0.w += w0[j] * z0[j].w;
                acc1.x += w1[j] * z1[j].x; acc1.y += w1[j] * z1[j].y;
                acc1.z += w1[j] * z1[j].z; acc1.w += w1[j] * z1[j].w;
            }
        }
    }
    float i0 = 1.0f / den0, i1 = 1.0f / den1;
    float4 o0, o1;
    o0.x = fmaxf(acc0.x * i0 + b0.x, 0.f); o0.y = fmaxf(acc0.y * i0 + b0.y, 0.f);
    o0.z = fmaxf(acc0.z * i0 + b0.z, 0.f); o0.w = fmaxf(acc0.w * i0 + b0.w, 0.f);
    o1.x = fmaxf(acc1.x * i1 + b1.x, 0.f); o1.y = fmaxf(acc1.y * i1 + b1.y, 0.f);
    o1.z = fmaxf(acc1.z * i1 + b1.z, 0.f); o1.w = fmaxf(acc1.w * i1 + b1.w, 0.f);
    *(float4*)(outb + (size_t)n * 256 + co) = o0;
    *(float4*)(outb + (size_t)n * 256 + 128 + co) = o1;
}

// ---------------- per-graph mean ----------------
__global__ void meanpart_kernel() {
    int g = blockIdx.x, s = blockIdx.y, inst = blockIdx.z, d = threadIdx.x;
    int beg = g_goff[inst * 65 + g], end = g_goff[inst * 65 + g + 1];
    const float* outb = g_gig + (size_t)inst * NN * 256;
    int cnt = end - beg;
    int chunk = (cnt + 15) / 16;
    int lo = beg + s * chunk;
    int hi = min(lo + chunk, end);
    float acc = 0.f;
    for (int r = lo; r < hi; r++) acc += outb[(size_t)r * 256 + d];
    g_part[((size_t)inst * 64 * 16 + g * 16 + s) * 256 + d] = acc;
}

__global__ void meanred_kernel() {
    int idx = blockIdx.x * 256 + threadIdx.x;
    int inst = blockIdx.y;
    if (idx >= 64 * 256) return;
    int g = idx >> 8;
    float acc = 0.f;
    for (int s = 0; s < 16; s++)
        acc += g_part[((size_t)inst * 64 * 16 + g * 16 + s) * 256 + (idx & 255)];
    float cnt = (float)(g_goff[inst * 65 + g + 1] - g_goff[inst * 65 + g]);
    g_hg[(size_t)inst * 64 * 256 + idx] = acc / fmaxf(cnt, 1.0f);
}

// ---------------- classifier ----------------
__global__ void classify_kernel(const float* __restrict__ Wc, const float* __restrict__ bc) {
    int idx = blockIdx.x * 256 + threadIdx.x;
    int inst = blockIdx.y;
    if (idx >= 64 * 2 * 32) return;
    int g = idx >> 6;
    int hh = (idx >> 5) & 1;
    int c = idx & 31;
    float s = bc[c];
    const float* hg = g_hg + (size_t)inst * 64 * 256 + g * 256 + hh * 128;
    const float* wr = Wc + c * 128;
    for (int d = 0; d < 128; d++) s += hg[d] * wr[d];
    g_logits[inst * 4096 + idx] = s;
}

// ---------------- combine ----------------
__global__ void combine_kernel(float* __restrict__ out) {
    int b = threadIdx.x;
    if (b >= 64) return;
    float dist[2];
    for (int hh = 0; hh < 2; hh++) {
        int base = b * 64 + hh * 32;
        float ss = 0.f;
        for (int c = 0; c < 32; c++) {
            float diff = g_logits[base + c] - g_logits[4096 + base + c] + 1e-6f;
            ss += diff * diff;
        }
        dist[hh] = sqrtf(ss);
    }
    float mx = fmaxf(dist[0], dist[1]);
    float e0 = expf(dist[0] - mx), e1 = expf(dist[1] - mx);
    float inv = 1.0f / (e0 + e1);
    out[b * 2 + 0] = e0 * inv;
    out[b * 2 + 1] = e1 * inv;
}

// ---------------- host ----------------
extern "C" void kernel_launch(void* const* d_in, const int* in_sizes, int n_in,
                              void* d_out, int out_size) {
    const float* f0 = (const float*)d_in[0];
    const float* f1 = (const float*)d_in[1];
    const int* src0 = (const int*)d_in[2];
    const int* dst0 = (const int*)d_in[3];
    const int* et0  = (const int*)d_in[4];
    const int* gid0 = (const int*)d_in[5];
    const int* src1 = (const int*)d_in[6];
    const int* dst1 = (const int*)d_in[7];
    const int* et1  = (const int*)d_in[8];
    const int* gid1 = (const int*)d_in[9];
    const float* W_et   = (const float*)d_in[10];
    const float* b_et   = (const float*)d_in[11];
    const float* W_ih   = (const float*)d_in[12];
    const float* W_hh   = (const float*)d_in[13];
    const float* b_ih   = (const float*)d_in[14];
    const float* b_hh   = (const float*)d_in[15];
    const float* W_fc   = (const float*)d_in[16];
    const float* attn_l = (const float*)d_in[17];
    const float* attn_r = (const float*)d_in[18];
    const float* gbias  = (const float*)d_in[19];
    const float* W_cls  = (const float*)d_in[20];
    const float* b_cls  = (const float*)d_in[21];

    float *p_gig, *p_zft, *p_cb, *p_zero;
    __nv_bfloat16 *p_cvhh, *p_cvhl, *p_cvah, *p_cval, *p_sh, *p_sl;
    __nv_bfloat16 *p_WAh, *p_WAl, *p_Wihh, *p_Wihl, *p_Whhh, *p_Whhl, *p_Wfch, *p_Wfcl;
    cudaGetSymbolAddress((void**)&p_gig, g_gig);
    cudaGetSymbolAddress((void**)&p_zft, g_zft);
    cudaGetSymbolAddress((void**)&p_cb, g_cb);
    cudaGetSymbolAddress((void**)&p_zero, g_zerobias);
    cudaGetSymbolAddress((void**)&p_cvhh, g_cvhh);
    cudaGetSymbolAddress((void**)&p_cvhl, g_cvhl);
    cudaGetSymbolAddress((void**)&p_cvah, g_cvah);
    cudaGetSymbolAddress((void**)&p_cval, g_cval);
    cudaGetSymbolAddress((void**)&p_sh, g_sh);
    cudaGetSymbolAddress((void**)&p_sl, g_sl);
    cudaGetSymbolAddress((void**)&p_WAh, g_WAh);
    cudaGetSymbolAddress((void**)&p_WAl, g_WAl);
    cudaGetSymbolAddress((void**)&p_Wihh, g_Wihh);
    cudaGetSymbolAddress((void**)&p_Wihl, g_Wihl);
    cudaGetSymbolAddress((void**)&p_Whhh, g_Whhh);
    cudaGetSymbolAddress((void**)&p_Whhl, g_Whhl);
    cudaGetSymbolAddress((void**)&p_Wfch, g_Wfch);
    cudaGetSymbolAddress((void**)&p_Wfcl, g_Wfcl);

    cudaFuncSetAttribute(gemm_mma<2, false, false>, cudaFuncAttributeMaxDynamicSharedMemorySize, SMEM_GEMM_BYTES);
    cudaFuncSetAttribute(gemm_mma<8, true, true>, cudaFuncAttributeMaxDynamicSharedMemorySize, SMEM_GEMM_BYTES);

    const int EB = (EE + 255) / 256;

    // fork-join resources
    cudaStream_t s1;
    cudaStreamCreateWithFlags(&s1, cudaStreamNonBlocking);
    cudaEvent_t evF[NSTEPS], evJ[NSTEPS];
    for (int i = 0; i < NSTEPS; i++) {
        cudaEventCreateWithFlags(&evF[i], cudaEventDisableTiming);
        cudaEventCreateWithFlags(&evJ[i], cudaEventDisableTiming);
    }

    // #1: prep (h init + weight splits + goff)
    prep_all<<<(2 * NN * 128 + 255) / 256, 256>>>(f0, f1, W_et, W_ih, W_hh, W_fc, gid0, gid1);
    // fork: gh step0 on s1, overlapped with CSR build on s0
    cudaEventRecord(evF[0], 0);
    cudaStreamWaitEvent(s1, evF[0], 0);
    gemm_mma<2, false, false><<<dim3(6, 391, 2), 256, SMEM_GEMM_BYTES, s1>>>(
        p_cvhh, p_cvhl, p_Whhh, p_Whhl, b_hh, nullptr, p_gig + 384, nullptr, nullptr, 768);
    cudaEventRecord(evJ[0], s1);
    // CSR build on s0 (parallel 3-phase scan)
    hist_kernel<<<dim3(EB, 2), 256>>>(dst0, et0, dst1, et1);
    scan1_kernel<<<dim3(NSB, 2), 256>>>();
    scan2_kernel<<<2, 512>>>();
    scan3_kernel<<<dim3(NSB, 2), 256>>>();
    scatter_kernel<<<dim3(EB, 2), 256>>>(src0, dst0, et0, src1, dst1, et1);

    for (int step = 0; step < NSTEPS; step++) {
        // s0: aggregate -> s-GEMM -> gi-GEMM (gh runs concurrently on s1)
        aggregate4_kernel<<<dim3(6250, 2), 256>>>(b_et);
        gemm_mma<8, true, true><<<dim3(2, 391, 2), 256, SMEM_GEMM_BYTES>>>(
            p_sh, p_sl, p_WAh, p_WAl, p_zero, p_cb, nullptr, p_cvah, p_cval, 128);
        gemm_mma<2, false, false><<<dim3(6, 391, 2), 256, SMEM_GEMM_BYTES>>>(
            p_cvah, p_cval, p_Wihh, p_Wihl, b_ih, nullptr, p_gig, nullptr, nullptr, 768);
        // join gh before GRU
        cudaStreamWaitEvent(0, evJ[step], 0);
        gru_kernel<<<(2 * NN * 32 + 255) / 256, 256>>>();
        if (step + 1 < NSTEPS) {
            cudaEventRecord(evF[step + 1], 0);
            cudaStreamWaitEvent(s1, evF[step + 1], 0);
            gemm_mma<2, false, false><<<dim3(6, 391, 2), 256, SMEM_GEMM_BYTES, s1>>>(
                p_cvhh, p_cvhl, p_Whhh, p_Whhl, b_hh, nullptr, p_gig + 384, nullptr, nullptr, 768);
            cudaEventRecord(evJ[step + 1], s1);
        }
    }

    normsig_kernel<<<12500, 256>>>();
    gemm_mma<2, false, false><<<dim3(4, 391, 2), 256, SMEM_GEMM_BYTES>>>(
        p_cvhh, p_cvhl, p_Wfch, p_Wfcl, p_zero, nullptr, p_zft, nullptr, nullptr, 256);
    elr_kernel<<<12500, 256>>>(attn_l, attn_r);
    gatfused_kernel<<<dim3(6250, 2), 256>>>(gbias);
    meanpart_kernel<<<dim3(64, 16, 2), 256>>>();
    meanred_kernel<<<dim3(64, 2), 256>>>();
    classify_kernel<<<dim3(16, 2), 256>>>(W_cls, b_cls);
    combine_kernel<<<1, 64>>>((float*)d_out);

    for (int i = 0; i < NSTEPS; i++) {
        cudaEventDestroy(evF[i]);
        cudaEventDestroy(evJ[i]);
    }
    cudaStreamDestroy(s1);
}

// round 17
// speedup vs baseline: 1.1416x; 1.1416x over previous
#include <cuda_runtime.h>
#include <cuda_bf16.h>
#include <math.h>

#define NN 50000
#define EE 600000
#define NSTEPS 5
#define NB4 (4 * NN + 1)    // CSR bins: (dst,etype)
#define NSB 391             // scan blocks: 391*512 >= 4*NN

// ---------------- scratch (device globals) ----------------
__device__ float g_gig[(size_t)2 * NN * 768];   // [gi(384) | gh(384)]; reused as GAT out [2N,256]
__device__ float g_h[(size_t)2 * NN * 128];
__device__ float g_cb[(size_t)2 * NN * 128];    // count-weighted b_et sum per node
__device__ float g_zft[(size_t)2 * NN * 256];
__device__ float g_el[2 * NN * 2];
__device__ float g_er[2 * NN * 2];
__device__ int   g_indptr[2 * NB4];
__device__ int   g_cursor[2 * NB4];
__device__ int   g_bsum[2][512];
__device__ int   g_eids[2 * EE];                // stores src directly (CSR by dst*4+et)
__device__ int   g_goff[2 * 65];
__device__ float g_part[2 * 64 * 16 * 256];
__device__ float g_hg[2 * 64 * 256];
__device__ float g_logits[2 * 64 * 2 * 32];
__device__ float g_zerobias[512];

// bf16 buffers (A operands split hi/lo; weights hi only — 2-term scheme)
__device__ __nv_bfloat16 g_cvhh[(size_t)2 * NN * 128];  // h split
__device__ __nv_bfloat16 g_cvhl[(size_t)2 * NN * 128];
__device__ __nv_bfloat16 g_sh[(size_t)2 * NN * 512];    // s (per-etype h sums) split
__device__ __nv_bfloat16 g_sl[(size_t)2 * NN * 512];
__device__ __nv_bfloat16 g_cvah[(size_t)2 * NN * 128];  // a split
__device__ __nv_bfloat16 g_cval[(size_t)2 * NN * 128];
__device__ __nv_bfloat16 g_WAh[128 * 512];              // stacked W_et: [o][k*128+d]
__device__ __nv_bfloat16 g_Wihh[384 * 128];
__device__ __nv_bfloat16 g_Whhh[384 * 128];
__device__ __nv_bfloat16 g_Wfch[256 * 128];

__device__ __forceinline__ float sigf(float x) { return 1.0f / (1.0f + expf(-x)); }
__device__ __forceinline__ float leakyf(float x) { return x > 0.0f ? x : 0.2f * x; }

__device__ __forceinline__ void split2(float x, __nv_bfloat16* hi, __nv_bfloat16* lo) {
    __nv_bfloat16 h = __float2bfloat16(x);
    *hi = h;
    *lo = __float2bfloat16(x - __bfloat162float(h));
}

__device__ __forceinline__ void split4_store(float4 v, __nv_bfloat16* hi, __nv_bfloat16* lo) {
    __nv_bfloat16 h0, h1, h2, h3, l0, l1, l2, l3;
    split2(v.x, &h0, &l0); split2(v.y, &h1, &l1);
    split2(v.z, &h2, &l2); split2(v.w, &h3, &l3);
    uint2 ph = make_uint2(((unsigned)__bfloat16_as_ushort(h1) << 16) | __bfloat16_as_ushort(h0),
                          ((unsigned)__bfloat16_as_ushort(h3) << 16) | __bfloat16_as_ushort(h2));
    uint2 pl = make_uint2(((unsigned)__bfloat16_as_ushort(l1) << 16) | __bfloat16_as_ushort(l0),
                          ((unsigned)__bfloat16_as_ushort(l3) << 16) | __bfloat16_as_ushort(l2));
    *(uint2*)hi = ph;
    *(uint2*)lo = pl;
}

// ---------------- prep: weight rounding + h init + cursor zero + graph offsets ----------------
__global__ void prep_all(const float* __restrict__ f0, const float* __restrict__ f1,
                         const float* __restrict__ Wet, const float* __restrict__ Wih,
                         const float* __restrict__ Whh, const float* __restrict__ Wfc,
                         const int* __restrict__ gid0, const int* __restrict__ gid1) {
    int idx = blockIdx.x * 256 + threadIdx.x;
    if (idx < 2 * NN * 128) {
        float x = (idx < NN * 128) ? f0[idx] : f1[idx - NN * 128];
        g_h[idx] = x;
        split2(x, g_cvhh + idx, g_cvhl + idx);
    }
    if (idx < 128 * 512) {   // stacked W_et: WA[o][k*128+d] = W_et[k][o][d]
        int o = idx >> 9, kk = idx & 511;
        int k = kk >> 7, d = kk & 127;
        g_WAh[idx] = __float2bfloat16(Wet[(k << 14) + (o << 7) + d]);
    }
    if (idx < 384 * 128) {
        g_Wihh[idx] = __float2bfloat16(Wih[idx]);
        g_Whhh[idx] = __float2bfloat16(Whh[idx]);
    }
    if (idx < 256 * 128) g_Wfch[idx] = __float2bfloat16(Wfc[idx]);
    if (idx < 2 * NB4) g_cursor[idx] = 0;
    if (idx < 2 * 65) {      // graph offsets by binary search on sorted gid
        int inst = idx / 65, g = idx % 65;
        const int* gid = inst ? gid1 : gid0;
        int lo = 0, hi = NN;
        while (lo < hi) {
            int mid = (lo + hi) >> 1;
            if (gid[mid] < g) lo = mid + 1; else hi = mid;
        }
        g_goff[idx] = lo;
    }
}

// ---------------- CSR build keyed by dst*4+etype ----------------
__global__ void hist_kernel(const int* __restrict__ d0, const int* __restrict__ e0,
                            const int* __restrict__ d1, const int* __restrict__ e1) {
    int i = blockIdx.x * 256 + threadIdx.x;
    if (i >= EE) return;
    int inst = blockIdx.y;
    const int* dst = inst ? d1 : d0;
    const int* et  = inst ? e1 : e0;
    atomicAdd(&g_cursor[inst * NB4 + dst[i] * 4 + et[i]], 1);
}

// 3-phase parallel exclusive scan of g_cursor[inst][0..4NN) -> g_indptr, g_cursor
__global__ void scan1_kernel() {
    int inst = blockIdx.y;
    int base = blockIdx.x * 512;
    int tid = threadIdx.x;
    const int n = 4 * NN;
    const int* cur = g_cursor + inst * NB4;
    int i0 = base + tid * 2;
    int v0 = (i0 < n) ? cur[i0] : 0;
    int v1 = (i0 + 1 < n) ? cur[i0 + 1] : 0;
    __shared__ int sm[256];
    sm[tid] = v0 + v1;
    __syncthreads();
    for (int o = 128; o; o >>= 1) {
        if (tid < o) sm[tid] += sm[tid + o];
        __syncthreads();
    }
    if (tid == 0) g_bsum[inst][blockIdx.x] = sm[0];
}

__global__ void scan2_kernel() {
    int inst = blockIdx.x;
    int tid = threadIdx.x;   // 512 threads
    __shared__ int sm[512];
    int v = (tid < NSB) ? g_bsum[inst][tid] : 0;
    sm[tid] = v;
    __syncthreads();
    for (int o = 1; o < 512; o <<= 1) {
        int t = (tid >= o) ? sm[tid - o] : 0;
        __syncthreads();
        sm[tid] += t;
        __syncthreads();
    }
    if (tid < NSB) g_bsum[inst][tid] = sm[tid] - v;   // exclusive
}

__global__ void scan3_kernel() {
    int inst = blockIdx.y;
    int base = blockIdx.x * 512;
    int tid = threadIdx.x;
    const int n = 4 * NN;
    int* cur = g_cursor + inst * NB4;
    int* ip = g_indptr + inst * NB4;
    int i0 = base + tid * 2;
    int v0 = (i0 < n) ? cur[i0] : 0;
    int v1 = (i0 + 1 < n) ? cur[i0 + 1] : 0;
    __shared__ int sm[256];
    int pair = v0 + v1;
    sm[tid] = pair;
    __syncthreads();
    for (int o = 1; o < 256; o <<= 1) {
        int t = (tid >= o) ? sm[tid - o] : 0;
        __syncthreads();
        sm[tid] += t;
        __syncthreads();
    }
    int excl = sm[tid] - pair + g_bsum[inst][blockIdx.x];
    if (i0 < n)     { ip[i0] = excl;        cur[i0] = excl; }
    if (i0 + 1 < n) { ip[i0 + 1] = excl + v0; cur[i0 + 1] = excl + v0; }
    if (blockIdx.x == 0 && tid == 0) ip[n] = EE;   // total is exactly EE
}

__global__ void scatter_kernel(const int* __restrict__ s0, const int* __restrict__ d0,
                               const int* __restrict__ e0, const int* __restrict__ s1,
                               const int* __restrict__ d1, const int* __restrict__ e1) {
    int i = blockIdx.x * 256 + threadIdx.x;
    if (i >= EE) return;
    int inst = blockIdx.y;
    const int* src = inst ? s1 : s0;
    const int* dst = inst ? d1 : d0;
    const int* et  = inst ? e1 : e0;
    int pos = atomicAdd(&g_cursor[inst * NB4 + dst[i] * 4 + et[i]], 1);
    g_eids[inst * EE + pos] = src[i];
}

// ---------------- tensor-core GEMM, K-chunked cp.async, 2-term split ----------------
__device__ __forceinline__ void ldsm_x4(unsigned& r0, unsigned& r1, unsigned& r2, unsigned& r3,
                                        unsigned addr) {
    asm volatile("ldmatrix.sync.aligned.m8n8.x4.shared.b16 {%0,%1,%2,%3}, [%4];\n"
                 : "=r"(r0), "=r"(r1), "=r"(r2), "=r"(r3) : "r"(addr));
}

__device__ __forceinline__ void mma_bf16(float* c, const unsigned* a, const unsigned* b) {
    asm volatile(
        "mma.sync.aligned.m16n8k16.row.col.f32.bf16.bf16.f32 "
        "{%0,%1,%2,%3},{%4,%5,%6,%7},{%8,%9},{%0,%1,%2,%3};\n"
        : "+f"(c[0]), "+f"(c[1]), "+f"(c[2]), "+f"(c[3])
        : "r"(a[0]), "r"(a[1]), "r"(a[2]), "r"(a[3]), "r"(b[0]), "r"(b[1]));
}

__device__ __forceinline__ void cp_async16(unsigned dst, const void* src, bool valid) {
    int sz = valid ? 16 : 0;
    asm volatile("cp.async.cg.shared.global [%0], [%1], 16, %2;\n"
                 :: "r"(dst), "l"(src), "r"(sz));
}

#define LDC 72   // padded chunk k-stride (elements): 144B rows, conflict-free ldmatrix
#define SMEM_GEMM_BYTES ((128 * LDC + 128 * LDC + 64 * LDC) * 2)   // 46080

// C[NN, nout] = (Ahi+Alo)[NN, CH*64] x B[nout, CH*64]^T, 2 MMA terms.
// SPLIT: bf16 split output (row stride 128). ROWADD: add rowadd[r*128+col].
template <int CH, bool SPLIT, bool ROWADD>
__global__ void __launch_bounds__(256, 3) gemm_mma(
    const __nv_bfloat16* __restrict__ Ahi, const __nv_bfloat16* __restrict__ Alo,
    const __nv_bfloat16* __restrict__ B,
    const float* __restrict__ bias, const float* __restrict__ rowadd,
    float* __restrict__ Cf, __nv_bfloat16* __restrict__ Csh, __nv_bfloat16* __restrict__ Csl,
    int rs)
{
    extern __shared__ __nv_bfloat16 sm[];
    __nv_bfloat16* sAh = sm;
    __nv_bfloat16* sAl = sAh + 128 * LDC;
    __nv_bfloat16* sBh = sAl + 128 * LDC;

    const int inst = blockIdx.z;
    const int KTOT = CH * 64;
    Ahi += (size_t)inst * NN * KTOT;
    Alo += (size_t)inst * NN * KTOT;
    if (SPLIT) {
        Csh += (size_t)inst * NN * 128;
        Csl += (size_t)inst * NN * 128;
    } else {
        Cf += (size_t)inst * NN * rs;
    }
    if (ROWADD) rowadd += (size_t)inst * NN * 128;

    const int tid = threadIdx.x;
    const int brow = blockIdx.y * 128;
    const int bcol = blockIdx.x * 64;

    const int wid = tid >> 5, lane = tid & 31;
    const int wr = (wid & 3) * 32;
    const int wc = (wid >> 2) * 32;

    float acc[2][4][4];
#pragma unroll
    for (int mi = 0; mi < 2; mi++)
#pragma unroll
        for (int nj = 0; nj < 4; nj++)
#pragma unroll
            for (int q = 0; q < 4; q++) acc[mi][nj][q] = 0.0f;

    const int la_r = lane & 15;
    const int la_c = (lane & 16) ? 8 : 0;
    const int lb_r = (lane & 7) + ((lane & 16) ? 8 : 0);
    const int lb_c = (lane & 8) ? 8 : 0;

    const unsigned baseAh = (unsigned)__cvta_generic_to_shared(sAh);
    const unsigned baseAl = (unsigned)__cvta_generic_to_shared(sAl);
    const unsigned baseBh = (unsigned)__cvta_generic_to_shared(sBh);

    for (int ch = 0; ch < CH; ch++) {
        if (ch) __syncthreads();
        const int ko = ch * 64;
#pragma unroll
        for (int it = 0; it < 4; it++) {
            int u = tid + it * 256;
            int r = u >> 3, cu = (u & 7) << 3;
            int gr = brow + r;
            bool v = gr < NN;
            size_t grc = v ? (size_t)gr : 0;
            cp_async16(baseAh + (r * LDC + cu) * 2, Ahi + grc * KTOT + ko + cu, v);
            cp_async16(baseAl + (r * LDC + cu) * 2, Alo + grc * KTOT + ko + cu, v);
        }
        {
            int u = tid;   // B: 512 16B units over 2 per thread
            int r = u >> 2, cu = (u & 3) << 4;
            // 64 rows x 64 elems = 512 units of 8 elems; use 2 units/thread contiguous
            cp_async16(baseBh + (r * LDC + cu) * 2, B + (size_t)(bcol + r) * KTOT + ko + cu, true);
            cp_async16(baseBh + (r * LDC + cu + 8) * 2, B + (size_t)(bcol + r) * KTOT + ko + cu + 8, true);
        }
        asm volatile("cp.async.commit_group;\n");
        asm volatile("cp.async.wait_group 0;\n");
        __syncthreads();

#pragma unroll
        for (int kc = 0; kc < 4; kc++) {
            const int k0 = kc * 16;
            unsigned ah[2][4], al[2][4], bh[4][2];
#pragma unroll
            for (int mi = 0; mi < 2; mi++) {
                unsigned off = (unsigned)(((wr + mi * 16 + la_r) * LDC + k0 + la_c) * 2);
                ldsm_x4(ah[mi][0], ah[mi][1], ah[mi][2], ah[mi][3], baseAh + off);
                ldsm_x4(al[mi][0], al[mi][1], al[mi][2], al[mi][3], baseAl + off);
            }
#pragma unroll
            for (int np = 0; np < 2; np++) {
                unsigned off = (unsigned)(((wc + np * 16 + lb_r) * LDC + k0 + lb_c) * 2);
                unsigned r0, r1, r2, r3;
                ldsm_x4(r0, r1, r2, r3, baseBh + off);
                bh[np * 2][0] = r0; bh[np * 2][1] = r1;
                bh[np * 2 + 1][0] = r2; bh[np * 2 + 1][1] = r3;
            }
#pragma unroll
            for (int mi = 0; mi < 2; mi++)
#pragma unroll
                for (int nj = 0; nj < 4; nj++) {
                    mma_bf16(acc[mi][nj], ah[mi], bh[nj]);
                    mma_bf16(acc[mi][nj], al[mi], bh[nj]);
                }
        }
    }

    const int g = lane >> 2, t4 = lane & 3;
#pragma unroll
    for (int mi = 0; mi < 2; mi++) {
#pragma unroll
        for (int nj = 0; nj < 4; nj++) {
            int col = bcol + wc + nj * 8 + t4 * 2;
            float bx = bias[col], by = bias[col + 1];
#pragma unroll
            for (int half = 0; half < 2; half++) {
                int r = brow + wr + mi * 16 + g + half * 8;
                if (r >= NN) continue;
                float v0 = acc[mi][nj][half * 2 + 0] + bx;
                float v1 = acc[mi][nj][half * 2 + 1] + by;
                if (ROWADD) {
                    v0 += rowadd[(size_t)r * 128 + col];
                    v1 += rowadd[(size_t)r * 128 + col + 1];
                }
                if (SPLIT) {
                    __nv_bfloat16 h0, h1, l0, l1;
                    split2(v0, &h0, &l0);
                    split2(v1, &h1, &l1);
                    unsigned ph = ((unsigned)__bfloat16_as_ushort(h1) << 16) | __bfloat16_as_ushort(h0);
                    unsigned pl = ((unsigned)__bfloat16_as_ushort(l1) << 16) | __bfloat16_as_ushort(l0);
                    *(unsigned*)(Csh + (size_t)r * 128 + col) = ph;
                    *(unsigned*)(Csl + (size_t)r * 128 + col) = pl;
                } else {
                    *(float2*)(Cf + (size_t)r * rs + col) = make_float2(v0, v1);
                }
            }
        }
    }
}

// ---------------- aggregate4: flattened bin loop + 4-edge MLP batching ----------------
__global__ void aggregate4_kernel(const float* __restrict__ b_et) {
    int inst = blockIdx.y;
    int n = blockIdx.x * 8 + (threadIdx.x >> 5);
    if (n >= NN) return;
    int lane = threadIdx.x & 31;
    const int* ip = g_indptr + inst * NB4 + n * 4;
    const int* eids = g_eids + (size_t)inst * EE;
    const float* hb = g_h + (size_t)inst * NN * 128;
    int b0 = ip[0], b1 = ip[1], b2 = ip[2], b3 = ip[3], b4 = ip[4];

    float4 a0 = make_float4(0.f, 0.f, 0.f, 0.f);
    float4 a1 = a0, a2 = a0, a3 = a0;
    int co = lane * 4;

    for (int i = b0; i < b4; i += 4) {
        int cnt = b4 - i;
        int s[4];
#pragma unroll
        for (int j = 0; j < 4; j++) s[j] = (j < cnt) ? eids[i + j] : s[0];
        float4 v[4];
#pragma unroll
        for (int j = 0; j < 4; j++) v[j] = *(const float4*)(hb + (size_t)s[j] * 128 + co);
#pragma unroll
        for (int j = 0; j < 4; j++) {
            if (j < cnt) {
                int e = i + j;
                int k = (e >= b1) + (e >= b2) + (e >= b3);   // warp-uniform
                float4 vv = v[j];
                if (k == 0)      { a0.x += vv.x; a0.y += vv.y; a0.z += vv.z; a0.w += vv.w; }
                else if (k == 1) { a1.x += vv.x; a1.y += vv.y; a1.z += vv.z; a1.w += vv.w; }
                else if (k == 2) { a2.x += vv.x; a2.y += vv.y; a2.z += vv.z; a2.w += vv.w; }
                else             { a3.x += vv.x; a3.y += vv.y; a3.z += vv.z; a3.w += vv.w; }
            }
        }
    }

    size_t so = ((size_t)inst * NN + n) * 512 + co;
    split4_store(a0, g_sh + so, g_sl + so);
    split4_store(a1, g_sh + so + 128, g_sl + so + 128);
    split4_store(a2, g_sh + so + 256, g_sl + so + 256);
    split4_store(a3, g_sh + so + 384, g_sl + so + 384);

    float c0 = (float)(b1 - b0), c1 = (float)(b2 - b1);
    float c2 = (float)(b3 - b2), c3 = (float)(b4 - b3);
    float4 e0 = *(const float4*)(b_et + co);
    float4 e1 = *(const float4*)(b_et + 128 + co);
    float4 e2 = *(const float4*)(b_et + 256 + co);
    float4 e3 = *(const float4*)(b_et + 384 + co);
    float4 cbv;
    cbv.x = c0 * e0.x + c1 * e1.x + c2 * e2.x + c3 * e3.x;
    cbv.y = c0 * e0.y + c1 * e1.y + c2 * e2.y + c3 * e3.y;
    cbv.z = c0 * e0.z + c1 * e1.z + c2 * e2.z + c3 * e3.z;
    cbv.w = c0 * e0.w + c1 * e1.w + c2 * e2.w + c3 * e3.w;
    *(float4*)(g_cb + ((size_t)inst * NN + n) * 128 + co) = cbv;
}

// ---------------- GRU elementwise (float4 per thread): h = (1-z)*nn + z*h ----------------
__global__ void gru_kernel() {
    int idx = blockIdx.x * 256 + threadIdx.x;
    if (idx >= 2 * NN * 32) return;
    int n = idx >> 5, c4 = (idx & 31) << 2;
    const float* gg = g_gig + (size_t)n * 768;
    float4 gir = *(const float4*)(gg + c4);
    float4 giz = *(const float4*)(gg + 128 + c4);
    float4 gin = *(const float4*)(gg + 256 + c4);
    float4 ghr = *(const float4*)(gg + 384 + c4);
    float4 ghz = *(const float4*)(gg + 512 + c4);
    float4 ghn = *(const float4*)(gg + 640 + c4);
    size_t ho = (size_t)n * 128 + c4;
    float4 hv = *(float4*)(g_h + ho);
    float4 o;
    {
        float r = sigf(gir.x + ghr.x), z = sigf(giz.x + ghz.x);
        o.x = (1.0f - z) * tanhf(gin.x + r * ghn.x) + z * hv.x;
    }
    {
        float r = sigf(gir.y + ghr.y), z = sigf(giz.y + ghz.y);
        o.y = (1.0f - z) * tanhf(gin.y + r * ghn.y) + z * hv.y;
    }
    {
        float r = sigf(gir.z + ghr.z), z = sigf(giz.z + ghz.z);
        o.z = (1.0f - z) * tanhf(gin.z + r * ghn.z) + z * hv.z;
    }
    {
        float r = sigf(gir.w + ghr.w), z = sigf(giz.w + ghz.w);
        o.w = (1.0f - z) * tanhf(gin.w + r * ghn.w) + z * hv.w;
    }
    *(float4*)(g_h + ho) = o;
    split4_store(o, g_cvhh + ho, g_cvhl + ho);
}

// ---------------- L2 normalize + sigmoid; emit h split ----------------
__global__ void normsig_kernel() {
    int w = (blockIdx.x * blockDim.x + threadIdx.x) >> 5;
    if (w >= 2 * NN) return;
    int lane = threadIdx.x & 31;
    size_t o = (size_t)w * 128 + lane * 4;
    float4 v = *(float4*)(g_h + o);
    float ss = v.x * v.x + v.y * v.y + v.z * v.z + v.w * v.w;
    for (int of = 16; of; of >>= 1) ss += __shfl_xor_sync(0xffffffff, ss, of);
    float inv = 1.0f / fmaxf(sqrtf(ss), 1e-12f);
    v.x = sigf(v.x * inv); v.y = sigf(v.y * inv);
    v.z = sigf(v.z * inv); v.w = sigf(v.w * inv);
    *(float4*)(g_h + o) = v;
    split4_store(v, g_cvhh + o, g_cvhl + o);
}

// ---------------- GAT: el/er per node ----------------
__global__ void elr_kernel(const float* __restrict__ al, const float* __restrict__ ar) {
    int w = (blockIdx.x * blockDim.x + threadIdx.x) >> 5;
    if (w >= 2 * NN) return;
    int lane = threadIdx.x & 31;
    float4 z0 = *(float4*)(g_zft + (size_t)w * 256 + lane * 4);
    float4 z1 = *(float4*)(g_zft + (size_t)w * 256 + 128 + lane * 4);
    float4 l0v = *(const float4*)(al + lane * 4);
    float4 l1v = *(const float4*)(al + 128 + lane * 4);
    float4 r0v = *(const float4*)(ar + lane * 4);
    float4 r1v = *(const float4*)(ar + 128 + lane * 4);
    float l0 = z0.x * l0v.x + z0.y * l0v.y + z0.z * l0v.z + z0.w * l0v.w;
    float l1 = z1.x * l1v.x + z1.y * l1v.y + z1.z * l1v.z + z1.w * l1v.w;
    float r0 = z0.x * r0v.x + z0.y * r0v.y + z0.z * r0v.z + z0.w * r0v.w;
    float r1 = z1.x * r1v.x + z1.y * r1v.y + z1.z * r1v.z + z1.w * r1v.w;
    for (int o = 16; o; o >>= 1) {
        l0 += __shfl_xor_sync(0xffffffff, l0, o);
        l1 += __shfl_xor_sync(0xffffffff, l1, o);
        r0 += __shfl_xor_sync(0xffffffff, r0, o);
        r1 += __shfl_xor_sync(0xffffffff, r1, o);
    }
    if (lane == 0) {
        g_el[w * 2 + 0] = l0; g_el[w * 2 + 1] = l1;
        g_er[w * 2 + 0] = r0; g_er[w * 2 + 1] = r1;
    }
}

// ---------------- GAT fused: max + den + weighted aggregate (4-edge batched) ----------------
__global__ void gatfused_kernel(const float* __restrict__ gbias) {
    int inst = blockIdx.y;
    int n = blockIdx.x * 8 + (threadIdx.x >> 5);
    if (n >= NN) return;
    int lane = threadIdx.x & 31;
    const int* ip = g_indptr + inst * NB4;
    int beg = ip[n * 4], end = ip[n * 4 + 4];
    const int* eids = g_eids + (size_t)inst * EE;
    float* outb = g_gig + (size_t)inst * NN * 256;
    float4 b0 = *(const float4*)(gbias + lane * 4);
    float4 b1 = *(const float4*)(gbias + 128 + lane * 4);
    if (beg == end) {
        float4 o0 = make_float4(fmaxf(b0.x, 0.f), fmaxf(b0.y, 0.f), fmaxf(b0.z, 0.f), fmaxf(b0.w, 0.f));
        float4 o1 = make_float4(fmaxf(b1.x, 0.f), fmaxf(b1.y, 0.f), fmaxf(b1.z, 0.f), fmaxf(b1.w, 0.f));
        *(float4*)(outb + (size_t)n * 256 + lane * 4) = o0;
        *(float4*)(outb + (size_t)n * 256 + 128 + lane * 4) = o1;
        return;
    }
    int nb = inst * NN + n;
    float er0 = g_er[nb * 2], er1 = g_er[nb * 2 + 1];
    const float* elb = g_el + (size_t)inst * NN * 2;
    float m0 = -INFINITY, m1 = -INFINITY;
    for (int i = beg + lane; i < end; i += 32) {
        int s = eids[i];
        m0 = fmaxf(m0, leakyf(elb[s * 2] + er0));
        m1 = fmaxf(m1, leakyf(elb[s * 2 + 1] + er1));
    }
    for (int o = 16; o; o >>= 1) {
        m0 = fmaxf(m0, __shfl_xor_sync(0xffffffff, m0, o));
        m1 = fmaxf(m1, __shfl_xor_sync(0xffffffff, m1, o));
    }
    float den0 = 0.f, den1 = 0.f;
    for (int i = beg + lane; i < end; i += 32) {
        int s = eids[i];
        den0 += expf(leakyf(elb[s * 2] + er0) - m0);
        den1 += expf(leakyf(elb[s * 2 + 1] + er1) - m1);
    }
    for (int o = 16; o; o >>= 1) {
        den0 += __shfl_xor_sync(0xffffffff, den0, o);
        den1 += __shfl_xor_sync(0xffffffff, den1, o);
    }
    float4 acc0 = make_float4(0.f, 0.f, 0.f, 0.f);
    float4 acc1 = make_float4(0.f, 0.f, 0.f, 0.f);
    int co = lane * 4;
    for (int i = beg; i < end; i += 4) {
        int cnt = end - i;
        int s[4];
#pragma unroll
        for (int j = 0; j < 4; j++) s[j] = (j < cnt) ? eids[i + j] : s[0];
        float w0[4], w1[4];
#pragma unroll
        for (int j = 0; j < 4; j++) {
            w0[j] = expf(leakyf(elb[s[j] * 2] + er0) - m0);
            w1[j] = expf(leakyf(elb[s[j] * 2 + 1] + er1) - m1);
        }
        float4 z0[4], z1[4];
#pragma unroll
        for (int j = 0; j < 4; j++) {
            size_t zb = ((size_t)inst * NN + s[j]) * 256;
            z0[j] = *(const float4*)(g_zft + zb + co);
            z1[j] = *(const float4*)(g_zft + zb + 128 + co);
        }
#pragma unroll
        for (int j = 0; j < 4; j++) {
            if (j < cnt) {
                acc0.x += w0[j] * z0[j].x; acc0.y += w0[j] * z0[j].y;
                acc0.z += w0[j] * z0[j].z; acc0.w += w0[j] * z0[j].w;
                acc1.x += w1[j] * z1[j].x; acc1.y += w1[j] * z1[j].y;
                acc1.z += w1[j] * z1[j].z; acc1.w += w1[j] * z1[j].w;
            }
        }
    }
    float i0 = 1.0f / den0, i1 = 1.0f / den1;
    float4 o0, o1;
    o0.x = fmaxf(acc0.x * i0 + b0.x, 0.f); o0.y = fmaxf(acc0.y * i0 + b0.y, 0.f);
    o0.z = fmaxf(acc0.z * i0 + b0.z, 0.f); o0.w = fmaxf(acc0.w * i0 + b0.w, 0.f);
    o1.x = fmaxf(acc1.x * i1 + b1.x, 0.f); o1.y = fmaxf(acc1.y * i1 + b1.y, 0.f);
    o1.z = fmaxf(acc1.z * i1 + b1.z, 0.f); o1.w = fmaxf(acc1.w * i1 + b1.w, 0.f);
    *(float4*)(outb + (size_t)n * 256 + co) = o0;
    *(float4*)(outb + (size_t)n * 256 + 128 + co) = o1;
}

// ---------------- per-graph mean ----------------
__global__ void meanpart_kernel() {
    int g = blockIdx.x, s = blockIdx.y, inst = blockIdx.z, d = threadIdx.x;
    int beg = g_goff[inst * 65 + g], end = g_goff[inst * 65 + g + 1];
    const float* outb = g_gig + (size_t)inst * NN * 256;
    int cnt = end - beg;
    int chunk = (cnt + 15) / 16;
    int lo = beg + s * chunk;
    int hi = min(lo + chunk, end);
    float acc = 0.f;
    for (int r = lo; r < hi; r++) acc += outb[(size_t)r * 256 + d];
    g_part[((size_t)inst * 64 * 16 + g * 16 + s) * 256 + d] = acc;
}

__global__ void meanred_kernel() {
    int idx = blockIdx.x * 256 + threadIdx.x;
    int inst = blockIdx.y;
    if (idx >= 64 * 256) return;
    int g = idx >> 8;
    float acc = 0.f;
    for (int s = 0; s < 16; s++)
        acc += g_part[((size_t)inst * 64 * 16 + g * 16 + s) * 256 + (idx & 255)];
    float cnt = (float)(g_goff[inst * 65 + g + 1] - g_goff[inst * 65 + g]);
    g_hg[(size_t)inst * 64 * 256 + idx] = acc / fmaxf(cnt, 1.0f);
}

// ---------------- classifier ----------------
__global__ void classify_kernel(const float* __restrict__ Wc, const float* __restrict__ bc) {
    int idx = blockIdx.x * 256 + threadIdx.x;
    int inst = blockIdx.y;
    if (idx >= 64 * 2 * 32) return;
    int g = idx >> 6;
    int hh = (idx >> 5) & 1;
    int c = idx & 31;
    float s = bc[c];
    const float* hg = g_hg + (size_t)inst * 64 * 256 + g * 256 + hh * 128;
    const float* wr = Wc + c * 128;
    for (int d = 0; d < 128; d++) s += hg[d] * wr[d];
    g_logits[inst * 4096 + idx] = s;
}

// ---------------- combine ----------------
__global__ void combine_kernel(float* __restrict__ out) {
    int b = threadIdx.x;
    if (b >= 64) return;
    float dist[2];
    for (int hh = 0; hh < 2; hh++) {
        int base = b * 64 + hh * 32;
        float ss = 0.f;
        for (int c = 0; c < 32; c++) {
            float diff = g_logits[base + c] - g_logits[4096 + base + c] + 1e-6f;
            ss += diff * diff;
        }
        dist[hh] = sqrtf(ss);
    }
    float mx = fmaxf(dist[0], dist[1]);
    float e0 = expf(dist[0] - mx), e1 = expf(dist[1] - mx);
    float inv = 1.0f / (e0 + e1);
    out[b * 2 + 0] = e0 * inv;
    out[b * 2 + 1] = e1 * inv;
}

// ---------------- host ----------------
extern "C" void kernel_launch(void* const* d_in, const int* in_sizes, int n_in,
                              void* d_out, int out_size) {
    const float* f0 = (const float*)d_in[0];
    const float* f1 = (const float*)d_in[1];
    const int* src0 = (const int*)d_in[2];
    const int* dst0 = (const int*)d_in[3];
    const int* et0  = (const int*)d_in[4];
    const int* gid0 = (const int*)d_in[5];
    const int* src1 = (const int*)d_in[6];
    const int* dst1 = (const int*)d_in[7];
    const int* et1  = (const int*)d_in[8];
    const int* gid1 = (const int*)d_in[9];
    const float* W_et   = (const float*)d_in[10];
    const float* b_et   = (const float*)d_in[11];
    const float* W_ih   = (const float*)d_in[12];
    const float* W_hh   = (const float*)d_in[13];
    const float* b_ih   = (const float*)d_in[14];
    const float* b_hh   = (const float*)d_in[15];
    const float* W_fc   = (const float*)d_in[16];
    const float* attn_l = (const float*)d_in[17];
    const float* attn_r = (const float*)d_in[18];
    const float* gbias  = (const float*)d_in[19];
    const float* W_cls  = (const float*)d_in[20];
    const float* b_cls  = (const float*)d_in[21];

    float *p_gig, *p_zft, *p_cb, *p_zero;
    __nv_bfloat16 *p_cvhh, *p_cvhl, *p_cvah, *p_cval, *p_sh, *p_sl;
    __nv_bfloat16 *p_WAh, *p_Wihh, *p_Whhh, *p_Wfch;
    cudaGetSymbolAddress((void**)&p_gig, g_gig);
    cudaGetSymbolAddress((void**)&p_zft, g_zft);
    cudaGetSymbolAddress((void**)&p_cb, g_cb);
    cudaGetSymbolAddress((void**)&p_zero, g_zerobias);
    cudaGetSymbolAddress((void**)&p_cvhh, g_cvhh);
    cudaGetSymbolAddress((void**)&p_cvhl, g_cvhl);
    cudaGetSymbolAddress((void**)&p_cvah, g_cvah);
    cudaGetSymbolAddress((void**)&p_cval, g_cval);
    cudaGetSymbolAddress((void**)&p_sh, g_sh);
    cudaGetSymbolAddress((void**)&p_sl, g_sl);
    cudaGetSymbolAddress((void**)&p_WAh, g_WAh);
    cudaGetSymbolAddress((void**)&p_Wihh, g_Wihh);
    cudaGetSymbolAddress((void**)&p_Whhh, g_Whhh);
    cudaGetSymbolAddress((void**)&p_Wfch, g_Wfch);

    cudaFuncSetAttribute(gemm_mma<2, false, false>, cudaFuncAttributeMaxDynamicSharedMemorySize, SMEM_GEMM_BYTES);
    cudaFuncSetAttribute(gemm_mma<8, true, true>, cudaFuncAttributeMaxDynamicSharedMemorySize, SMEM_GEMM_BYTES);

    const int EB = (EE + 255) / 256;

    // fork-join resources
    cudaStream_t s1;
    cudaStreamCreateWithFlags(&s1, cudaStreamNonBlocking);
    cudaEvent_t evF[NSTEPS], evJ[NSTEPS];
    for (int i = 0; i < NSTEPS; i++) {
        cudaEventCreateWithFlags(&evF[i], cudaEventDisableTiming);
        cudaEventCreateWithFlags(&evJ[i], cudaEventDisableTiming);
    }

    // #1: prep (h init + weight rounding + goff)
    prep_all<<<(2 * NN * 128 + 255) / 256, 256>>>(f0, f1, W_et, W_ih, W_hh, W_fc, gid0, gid1);
    // fork: gh step0 on s1, overlapped with CSR build on s0
    cudaEventRecord(evF[0], 0);
    cudaStreamWaitEvent(s1, evF[0], 0);
    gemm_mma<2, false, false><<<dim3(6, 391, 2), 256, SMEM_GEMM_BYTES, s1>>>(
        p_cvhh, p_cvhl, p_Whhh, b_hh, nullptr, p_gig + 384, nullptr, nullptr, 768);
    cudaEventRecord(evJ[0], s1);
    // CSR build on s0 (parallel 3-phase scan)
    hist_kernel<<<dim3(EB, 2), 256>>>(dst0, et0, dst1, et1);
    scan1_kernel<<<dim3(NSB, 2), 256>>>();
    scan2_kernel<<<2, 512>>>();
    scan3_kernel<<<dim3(NSB, 2), 256>>>();
    scatter_kernel<<<dim3(EB, 2), 256>>>(src0, dst0, et0, src1, dst1, et1);

    for (int step = 0; step < NSTEPS; step++) {
        // s0: aggregate -> s-GEMM -> gi-GEMM (gh runs concurrently on s1)
        aggregate4_kernel<<<dim3(6250, 2), 256>>>(b_et);
        gemm_mma<8, true, true><<<dim3(2, 391, 2), 256, SMEM_GEMM_BYTES>>>(
            p_sh, p_sl, p_WAh, p_zero, p_cb, nullptr, p_cvah, p_cval, 128);
        gemm_mma<2, false, false><<<dim3(6, 391, 2), 256, SMEM_GEMM_BYTES>>>(
            p_cvah, p_cval, p_Wihh, b_ih, nullptr, p_gig, nullptr, nullptr, 768);
        // join gh before GRU
        cudaStreamWaitEvent(0, evJ[step], 0);
        gru_kernel<<<(2 * NN * 32 + 255) / 256, 256>>>();
        if (step + 1 < NSTEPS) {
            cudaEventRecord(evF[step + 1], 0);
            cudaStreamWaitEvent(s1, evF[step + 1], 0);
            gemm_mma<2, false, false><<<dim3(6, 391, 2), 256, SMEM_GEMM_BYTES, s1>>>(
                p_cvhh, p_cvhl, p_Whhh, b_hh, nullptr, p_gig + 384, nullptr, nullptr, 768);
            cudaEventRecord(evJ[step + 1], s1);
        }
    }

    normsig_kernel<<<12500, 256>>>();
    gemm_mma<2, false, false><<<dim3(4, 391, 2), 256, SMEM_GEMM_BYTES>>>(
        p_cvhh, p_cvhl, p_Wfch, p_zero, nullptr, p_zft, nullptr, nullptr, 256);
    elr_kernel<<<12500, 256>>>(attn_l, attn_r);
    gatfused_kernel<<<dim3(6250, 2), 256>>>(gbias);
    meanpart_kernel<<<dim3(64, 16, 2), 256>>>();
    meanred_kernel<<<dim3(64, 2), 256>>>();
    classify_kernel<<<dim3(16, 2), 256>>>(W_cls, b_cls);
    combine_kernel<<<1, 64>>>((float*)d_out);

    for (int i = 0; i < NSTEPS; i++) {
        cudaEventDestroy(evF[i]);
        cudaEventDestroy(evJ[i]);
    }
    cudaStreamDestroy(s1);
}